// round 1
// baseline (speedup 1.0000x reference)
#include <cuda_runtime.h>

// Problem constants (fixed by the dataset)
#define BB    8
#define NN    1024
#define RR    8192
#define DIN   32
#define NF    128
#define DOUT  3
#define PSTEPS 3
#define MREL  (BB * RR)   // 65536 relation rows
#define MPART (BB * NN)   // 8192 particle rows

typedef unsigned long long u64;

// ---------------- scratch (device globals; no allocations allowed) ----------
__device__ float g_buf0[MREL * NF];      // 32 MB
__device__ float g_buf1[MREL * NF];      // 32 MB
__device__ float g_relenc[MREL * NF];    // 32 MB
__device__ float g_pencode[MPART * NF];  // 4 MB
__device__ float g_peffect[MPART * NF];  // 4 MB
__device__ float g_eagg[MPART * NF];     // 4 MB
__device__ float g_ptmp[MPART * NF];     // 4 MB
__device__ int   g_recv[MREL];
__device__ int   g_send[MREL];

// ---------------- f32x2 packed-FMA helpers ----------------------------------
__device__ __forceinline__ void fma2(u64 &d, u64 a, u64 b) {
    asm volatile("fma.rn.f32x2 %0, %1, %2, %0;" : "+l"(d) : "l"(a), "l"(b));
}
__device__ __forceinline__ u64 dup2(float x) {
    u64 r; asm("mov.b64 %0, {%1, %1};" : "=l"(r) : "f"(x)); return r;
}
__device__ __forceinline__ float2 unpack2(u64 v) {
    float2 f; asm("mov.b64 {%0, %1}, %2;" : "=f"(f.x), "=f"(f.y) : "l"(v)); return f;
}

// ---------------- index extraction from dense one-hot Rr/Rs -----------------
// Rr/Rs: [B, N, R] row-major; exactly one nonzero (=1.0) per (b, :, r) column.
__global__ void extract_idx_kernel(const float4* __restrict__ Rr,
                                   const float4* __restrict__ Rs,
                                   int* __restrict__ recv, int* __restrict__ send)
{
    const long long total = (long long)BB * NN * RR / 4;  // 16M float4
    const long long stride = (long long)gridDim.x * blockDim.x;
    for (long long i = blockIdx.x * (long long)blockDim.x + threadIdx.x;
         i < total; i += stride) {
        float4 v = Rr[i];
        if (v.x != 0.f || v.y != 0.f || v.z != 0.f || v.w != 0.f) {
            long long e = i * 4;
            int b = (int)(e >> 23);            // N*R = 2^23
            int n = (int)((e >> 13) & (NN - 1));
            int r = (int)(e & (RR - 1));
            int* o = recv + b * RR + r;
            if (v.x != 0.f) o[0] = n;
            if (v.y != 0.f) o[1] = n;
            if (v.z != 0.f) o[2] = n;
            if (v.w != 0.f) o[3] = n;
        }
        float4 w = Rs[i];
        if (w.x != 0.f || w.y != 0.f || w.z != 0.f || w.w != 0.f) {
            long long e = i * 4;
            int b = (int)(e >> 23);
            int n = (int)((e >> 13) & (NN - 1));
            int r = (int)(e & (RR - 1));
            int* o = send + b * RR + r;
            if (w.x != 0.f) o[0] = n;
            if (w.y != 0.f) o[1] = n;
            if (w.z != 0.f) o[2] = n;
            if (w.w != 0.f) o[3] = n;
        }
    }
}

__global__ void zero_kernel(float4* __restrict__ p) {
    int i = blockIdx.x * blockDim.x + threadIdx.x;
    p[i] = make_float4(0.f, 0.f, 0.f, 0.f);
}

// ---------------- fused SGEMM: C[M,128] = epi(A_virtual[M,K] @ W[K,128]) -----
enum { A_PLAIN = 0, A_RELENC = 1, A_RELPROP = 2, A_PARTPROP = 3 };
enum { E_RELU = 0, E_SCATTER = 1, E_RESID = 2 };

#define BM 128
#define BK 16
#define LDA_S 132   // k-major A tile stride (pad; multiple of 4 for alignment)

template<int MODE_A, int MODE_EPI>
__global__ __launch_bounds__(256, 2)
void gemm128(const float* __restrict__ A, const float* __restrict__ W,
             const float* __restrict__ bias, float* __restrict__ C,
             const float* __restrict__ src0,
             const int* __restrict__ recvp, const int* __restrict__ sendp,
             int K)
{
    __shared__ __align__(16) float As[BK][LDA_S];
    __shared__ __align__(16) float Ws[BK][NF];
    __shared__ int recv_s[BM];
    __shared__ int send_s[BM];

    const int tid  = threadIdx.x;
    const int row0 = blockIdx.x * BM;
    const int tx   = tid & 15;   // 16 col groups x 8 cols = 128
    const int ty   = tid >> 4;   // 16 row groups x 8 rows = 128

    if (MODE_A == A_RELENC || MODE_A == A_RELPROP) {
        if (tid < BM) {
            recv_s[tid] = recvp[row0 + tid];
            send_s[tid] = sendp[row0 + tid];
        }
        __syncthreads();
    }

    u64 acc[4][8];
    #pragma unroll
    for (int i = 0; i < 4; ++i)
        #pragma unroll
        for (int j = 0; j < 8; ++j) acc[i][j] = 0ull;

    const int nchunk = (K + BK - 1) / BK;
    for (int kt = 0; kt < nchunk; ++kt) {
        const int k0 = kt * BK;
        // ---- A tile (fused gather depending on mode), stored k-major ----
        #pragma unroll
        for (int i = 0; i < 8; ++i) {
            int flat = tid + i * 256;
            int rl = flat >> 4;
            int c  = flat & 15;
            int kg = k0 + c;
            int grow = row0 + rl;
            float v = 0.f;
            if (kg < K) {
                if (MODE_A == A_PLAIN) {
                    v = A[(long long)grow * K + kg];
                } else if (MODE_A == A_RELENC) {
                    int b = grow >> 13;                      // R = 2^13
                    if (kg < DIN)
                        v = src0[((b << 10) + recv_s[rl]) * DIN + kg];
                    else if (kg < 2 * DIN)
                        v = src0[((b << 10) + send_s[rl]) * DIN + (kg - DIN)];
                    else
                        v = A[grow];                         // Ra (REL_D = 1)
                } else if (MODE_A == A_RELPROP) {
                    int b = grow >> 13;
                    if (kg < NF)
                        v = A[(long long)grow * NF + kg];    // relation_encode
                    else if (kg < 2 * NF)
                        v = src0[((b << 10) + recv_s[rl]) * NF + (kg - NF)];
                    else
                        v = src0[((b << 10) + send_s[rl]) * NF + (kg - 2 * NF)];
                } else { // A_PARTPROP
                    if (kg < NF) v = A[grow * NF + kg];           // particle_encode
                    else         v = src0[grow * NF + (kg - NF)]; // effect_agg
                }
            }
            As[c][rl] = v;
        }
        // ---- W tile ----
        #pragma unroll
        for (int i = 0; i < 8; ++i) {
            int flat = tid + i * 256;
            int kk = flat >> 7;
            int n  = flat & 127;
            int kg = k0 + kk;
            Ws[kk][n] = (kg < K) ? W[kg * NF + n] : 0.f;
        }
        __syncthreads();
        // ---- compute: row-pairs packed into f32x2 ----
        #pragma unroll
        for (int kk = 0; kk < BK; ++kk) {
            u64 a2[4];
            #pragma unroll
            for (int i = 0; i < 4; ++i)
                a2[i] = *reinterpret_cast<const u64*>(&As[kk][ty * 8 + 2 * i]);
            float4 w0 = *reinterpret_cast<const float4*>(&Ws[kk][tx * 8]);
            float4 w1 = *reinterpret_cast<const float4*>(&Ws[kk][tx * 8 + 4]);
            u64 wd[8] = { dup2(w0.x), dup2(w0.y), dup2(w0.z), dup2(w0.w),
                          dup2(w1.x), dup2(w1.y), dup2(w1.z), dup2(w1.w) };
            #pragma unroll
            for (int i = 0; i < 4; ++i)
                #pragma unroll
                for (int j = 0; j < 8; ++j)
                    fma2(acc[i][j], a2[i], wd[j]);
        }
        __syncthreads();
    }

    // ---- epilogue ----
    float4 b0 = *reinterpret_cast<const float4*>(&bias[tx * 8]);
    float4 b1 = *reinterpret_cast<const float4*>(&bias[tx * 8 + 4]);
    float bb[8] = { b0.x, b0.y, b0.z, b0.w, b1.x, b1.y, b1.z, b1.w };

    #pragma unroll
    for (int i = 0; i < 4; ++i) {
        float rowv[2][8];
        #pragma unroll
        for (int j = 0; j < 8; ++j) {
            float2 f = unpack2(acc[i][j]);
            rowv[0][j] = f.x + bb[j];
            rowv[1][j] = f.y + bb[j];
        }
        #pragma unroll
        for (int h = 0; h < 2; ++h) {
            int rl = ty * 8 + 2 * i + h;
            int grow = row0 + rl;
            if (MODE_EPI == E_RELU) {
                float4 o0 = make_float4(fmaxf(rowv[h][0], 0.f), fmaxf(rowv[h][1], 0.f),
                                        fmaxf(rowv[h][2], 0.f), fmaxf(rowv[h][3], 0.f));
                float4 o1 = make_float4(fmaxf(rowv[h][4], 0.f), fmaxf(rowv[h][5], 0.f),
                                        fmaxf(rowv[h][6], 0.f), fmaxf(rowv[h][7], 0.f));
                float4* cp = reinterpret_cast<float4*>(&C[(long long)grow * NF + tx * 8]);
                cp[0] = o0; cp[1] = o1;
            } else if (MODE_EPI == E_RESID) {
                float4* cp = reinterpret_cast<float4*>(&C[(long long)grow * NF + tx * 8]);
                float4 r0 = cp[0], r1 = cp[1];
                float4 o0 = make_float4(fmaxf(rowv[h][0] + r0.x, 0.f), fmaxf(rowv[h][1] + r0.y, 0.f),
                                        fmaxf(rowv[h][2] + r0.z, 0.f), fmaxf(rowv[h][3] + r0.w, 0.f));
                float4 o1 = make_float4(fmaxf(rowv[h][4] + r1.x, 0.f), fmaxf(rowv[h][5] + r1.y, 0.f),
                                        fmaxf(rowv[h][6] + r1.z, 0.f), fmaxf(rowv[h][7] + r1.w, 0.f));
                cp[0] = o0; cp[1] = o1;
            } else { // E_SCATTER: effect_agg[b, recv[row], :] += relu(relation_effect)
                int b = grow >> 13;
                float* dst = &C[(long long)((b << 10) + recv_s[rl]) * NF + tx * 8];
                #pragma unroll
                for (int j = 0; j < 8; ++j)
                    atomicAdd(dst + j, fmaxf(rowv[h][j], 0.f));
            }
        }
    }
}

// ---------------- final predictor layer: [8192,128] @ [128,3] + b -----------
__global__ void pred_final_kernel(const float* __restrict__ X, const float* __restrict__ W,
                                  const float* __restrict__ bias, float* __restrict__ out)
{
    __shared__ float Ws[NF * DOUT];
    __shared__ float bs[DOUT];
    int tid = threadIdx.x;
    for (int i = tid; i < NF * DOUT; i += blockDim.x) Ws[i] = W[i];
    if (tid < DOUT) bs[tid] = bias[tid];
    __syncthreads();
    int p = blockIdx.x * blockDim.x + tid;
    float a0 = bs[0], a1 = bs[1], a2 = bs[2];
    const float4* xp = reinterpret_cast<const float4*>(X + (long long)p * NF);
    #pragma unroll
    for (int k4 = 0; k4 < NF / 4; ++k4) {
        float4 x = xp[k4];
        int k = k4 * 4;
        a0 += x.x * Ws[k * 3 + 0] + x.y * Ws[(k + 1) * 3 + 0] +
              x.z * Ws[(k + 2) * 3 + 0] + x.w * Ws[(k + 3) * 3 + 0];
        a1 += x.x * Ws[k * 3 + 1] + x.y * Ws[(k + 1) * 3 + 1] +
              x.z * Ws[(k + 2) * 3 + 1] + x.w * Ws[(k + 3) * 3 + 1];
        a2 += x.x * Ws[k * 3 + 2] + x.y * Ws[(k + 1) * 3 + 2] +
              x.z * Ws[(k + 2) * 3 + 2] + x.w * Ws[(k + 3) * 3 + 2];
    }
    out[p * 3 + 0] = a0;
    out[p * 3 + 1] = a1;
    out[p * 3 + 2] = a2;
}

// ---------------- host orchestration ----------------------------------------
extern "C" void kernel_launch(void* const* d_in, const int* in_sizes, int n_in,
                              void* d_out, int out_size)
{
    const float* state = (const float*)d_in[0];
    const float* Rr    = (const float*)d_in[1];
    const float* Rs    = (const float*)d_in[2];
    const float* Ra    = (const float*)d_in[3];
    // d_in[4] = pstep (fixed = 3)
    const float* pe_w0 = (const float*)d_in[5],  *pe_b0 = (const float*)d_in[6];
    const float* pe_w1 = (const float*)d_in[7],  *pe_b1 = (const float*)d_in[8];
    const float* re_w0 = (const float*)d_in[9],  *re_b0 = (const float*)d_in[10];
    const float* re_w1 = (const float*)d_in[11], *re_b1 = (const float*)d_in[12];
    const float* re_w2 = (const float*)d_in[13], *re_b2 = (const float*)d_in[14];
    const float* rp_w  = (const float*)d_in[15], *rp_b  = (const float*)d_in[16];
    const float* pp_w  = (const float*)d_in[17], *pp_b  = (const float*)d_in[18];
    const float* pr_w0 = (const float*)d_in[19], *pr_b0 = (const float*)d_in[20];
    const float* pr_w1 = (const float*)d_in[21], *pr_b1 = (const float*)d_in[22];
    float* out = (float*)d_out;

    float *buf0, *buf1, *relenc, *pencode, *peffect, *eagg, *ptmp;
    int *recv, *send;
    cudaGetSymbolAddress((void**)&buf0,    g_buf0);
    cudaGetSymbolAddress((void**)&buf1,    g_buf1);
    cudaGetSymbolAddress((void**)&relenc,  g_relenc);
    cudaGetSymbolAddress((void**)&pencode, g_pencode);
    cudaGetSymbolAddress((void**)&peffect, g_peffect);
    cudaGetSymbolAddress((void**)&eagg,    g_eagg);
    cudaGetSymbolAddress((void**)&ptmp,    g_ptmp);
    cudaGetSymbolAddress((void**)&recv,    g_recv);
    cudaGetSymbolAddress((void**)&send,    g_send);

    // 1) one-hot -> indices (single full read of Rr/Rs; never touched again)
    extract_idx_kernel<<<2048, 256>>>((const float4*)Rr, (const float4*)Rs, recv, send);

    // 2) relation encoder: relu(relu(relu([state_r|state_s|Ra] @ w0) @ w1) @ w2)
    gemm128<A_RELENC, E_RELU><<<MREL / BM, 256>>>(Ra, re_w0, re_b0, buf0, state, recv, send, 2 * DIN + 1);
    gemm128<A_PLAIN,  E_RELU><<<MREL / BM, 256>>>(buf0, re_w1, re_b1, buf1, nullptr, nullptr, nullptr, NF);
    gemm128<A_PLAIN,  E_RELU><<<MREL / BM, 256>>>(buf1, re_w2, re_b2, relenc, nullptr, nullptr, nullptr, NF);

    // 3) particle encoder: relu(relu(state @ w0) @ w1)
    gemm128<A_PLAIN, E_RELU><<<MPART / BM, 256>>>(state, pe_w0, pe_b0, ptmp, nullptr, nullptr, nullptr, DIN);
    gemm128<A_PLAIN, E_RELU><<<MPART / BM, 256>>>(ptmp, pe_w1, pe_b1, pencode, nullptr, nullptr, nullptr, NF);

    // 4) propagation: particle_effect starts at zero
    zero_kernel<<<MPART * NF / 4 / 256, 256>>>((float4*)peffect);
    for (int s = 0; s < PSTEPS; ++s) {
        zero_kernel<<<MPART * NF / 4 / 256, 256>>>((float4*)eagg);
        // relation propagator with fused gather of effects + fused scatter-add
        gemm128<A_RELPROP, E_SCATTER><<<MREL / BM, 256>>>(relenc, rp_w, rp_b, eagg,
                                                          peffect, recv, send, 3 * NF);
        // particle propagator: relu([pencode|eagg] @ pp_w + pp_b + peffect), in place
        gemm128<A_PARTPROP, E_RESID><<<MPART / BM, 256>>>(pencode, pp_w, pp_b, peffect,
                                                          eagg, nullptr, nullptr, 2 * NF);
    }

    // 5) predictor
    gemm128<A_PLAIN, E_RELU><<<MPART / BM, 256>>>(peffect, pr_w0, pr_b0, ptmp, nullptr, nullptr, nullptr, NF);
    pred_final_kernel<<<MPART / 256, 256>>>(ptmp, pr_w1, pr_b1, out);
}

// round 3
// speedup vs baseline: 2.2712x; 2.2712x over previous
#include <cuda_runtime.h>
#include <cuda_bf16.h>
#include <cstdint>

#define BB    8
#define NN    1024
#define RR    8192
#define DIN   32
#define NF    128
#define DOUT  3
#define PSTEPS 3
#define MREL  (BB * RR)   // 65536
#define MPART (BB * NN)   // 8192

// ---------------- scratch (device globals) ----------------------------------
__device__ float g_buf0[MREL * NF];
__device__ float g_buf1[MREL * NF];
__device__ float g_relenc[MREL * NF];
__device__ float g_pencode[MPART * NF];
__device__ float g_peffect[MPART * NF];
__device__ float g_eagg[MPART * NF];
__device__ float g_ptmp[MPART * NF];
__device__ int   g_recv[MREL];
__device__ int   g_send[MREL];
// packed weights: [Kpad/2][128] u32 (bf16x2 of k,k+1 per col n), hi & lo planes
#define WT_U32 81920
__device__ uint32_t g_wh[WT_U32];
__device__ uint32_t g_wl[WT_U32];
// u32 offsets per matrix (Kpad/2 * 128)
#define WO_PE0 0        // Kpad 32
#define WO_PE1 2048     // 128
#define WO_RE0 10240    // 96 (K=65)
#define WO_RE1 16384    // 128
#define WO_RE2 24576    // 128
#define WO_RP  32768    // 384
#define WO_PP  57344    // 256
#define WO_PR0 73728    // 128

// ---------------- helpers ----------------------------------------------------
__device__ __forceinline__ uint32_t packbf(float vlo, float vhi) {
    // result: low 16 bits = bf16(vlo), high 16 = bf16(vhi)
    uint32_t r;
    asm("cvt.rn.bf16x2.f32 %0, %1, %2;" : "=r"(r) : "f"(vhi), "f"(vlo));
    return r;
}
__device__ __forceinline__ void mma16816(float* d, const uint32_t* a, uint32_t b0, uint32_t b1) {
    asm volatile("mma.sync.aligned.m16n8k16.row.col.f32.bf16.bf16.f32 "
                 "{%0,%1,%2,%3}, {%4,%5,%6,%7}, {%8,%9}, {%0,%1,%2,%3};"
                 : "+f"(d[0]), "+f"(d[1]), "+f"(d[2]), "+f"(d[3])
                 : "r"(a[0]), "r"(a[1]), "r"(a[2]), "r"(a[3]), "r"(b0), "r"(b1));
}

// ---------------- index extraction from dense one-hot Rr/Rs -----------------
__global__ void extract_idx_kernel(const float4* __restrict__ Rr,
                                   const float4* __restrict__ Rs,
                                   int* __restrict__ recv, int* __restrict__ send)
{
    const long long total = (long long)BB * NN * RR / 4;
    const long long stride = (long long)gridDim.x * blockDim.x;
    for (long long i = blockIdx.x * (long long)blockDim.x + threadIdx.x;
         i < total; i += stride) {
        float4 v = Rr[i];
        if (v.x != 0.f || v.y != 0.f || v.z != 0.f || v.w != 0.f) {
            long long e = i * 4;
            int b = (int)(e >> 23);
            int n = (int)((e >> 13) & (NN - 1));
            int r = (int)(e & (RR - 1));
            int* o = recv + b * RR + r;
            if (v.x != 0.f) o[0] = n;
            if (v.y != 0.f) o[1] = n;
            if (v.z != 0.f) o[2] = n;
            if (v.w != 0.f) o[3] = n;
        }
        float4 w = Rs[i];
        if (w.x != 0.f || w.y != 0.f || w.z != 0.f || w.w != 0.f) {
            long long e = i * 4;
            int b = (int)(e >> 23);
            int n = (int)((e >> 13) & (NN - 1));
            int r = (int)(e & (RR - 1));
            int* o = send + b * RR + r;
            if (w.x != 0.f) o[0] = n;
            if (w.y != 0.f) o[1] = n;
            if (w.z != 0.f) o[2] = n;
            if (w.w != 0.f) o[3] = n;
        }
    }
}

__global__ void zero_kernel(float4* __restrict__ p) {
    int i = blockIdx.x * blockDim.x + threadIdx.x;
    p[i] = make_float4(0.f, 0.f, 0.f, 0.f);
}

// ---------------- weight transpose + split to packed bf16x2 pairs -----------
__global__ void split_w_kernel(const float* __restrict__ w,
                               uint32_t* __restrict__ hi, uint32_t* __restrict__ lo,
                               int K, int Kpad)
{
    int idx = blockIdx.x * blockDim.x + threadIdx.x;
    if (idx >= (Kpad / 2) * 128) return;
    int k2 = idx >> 7, n = idx & 127;
    int k0 = 2 * k2;
    float v0 = (k0 < K)     ? w[(size_t)k0 * 128 + n]       : 0.f;
    float v1 = (k0 + 1 < K) ? w[(size_t)(k0 + 1) * 128 + n] : 0.f;
    uint32_t h = packbf(v0, v1);
    float h0 = __uint_as_float(h << 16);
    float h1 = __uint_as_float(h & 0xFFFF0000u);
    hi[idx] = h;
    lo[idx] = packbf(v0 - h0, v1 - h1);
}

// ---------------- fused mma.sync GEMM: C[M,128] = epi(A_virt[M,K] @ W) ------
enum { A_PLAIN = 0, A_RELENC = 1, A_RELPROP = 2, A_PARTPROP = 3 };
enum { E_RELU = 0, E_SCATTER = 1, E_RESID = 2 };

// smem layout (bytes). A row stride 80B (20 u32), W row stride 544B (136 u32).
#define SM_BIAS 0
#define SM_RECV 512
#define SM_SEND 1024
#define SM_A    1536
#define AHI_OFF(s) (SM_A + (s) * 10240)
#define ALO_OFF(s) (SM_A + 20480 + (s) * 10240)
#define SM_W    (SM_A + 40960)
#define WHI_OFF(s) (SM_W + (s) * 8704)
#define WLO_OFF(s) (SM_W + 17408 + (s) * 8704)
#define SMEM_TOTAL_B (SM_W + 34816)   // 77312 bytes

template<int MODE_A>
__device__ __forceinline__ void fill_tile(
    char* smem, int s, int kt,
    const float* __restrict__ A,
    const uint32_t* __restrict__ Whp, const uint32_t* __restrict__ Wlp,
    const float* __restrict__ src0,
    const int* recv_s, const int* send_s,
    int row0, int K, int tid)
{
    // ---- A: 128 rows x 32 k, each thread: one row-half (16 floats) ----
    const int row   = tid >> 1;
    const int half  = tid & 1;
    const int kbase = kt * 32 + half * 16;
    const int grow  = row0 + row;
    float x[16];
    const float* p = nullptr;
    bool zero = false, special = false;

    if (MODE_A == A_PLAIN) {
        if (kbase < K) p = A + (size_t)grow * K + kbase; else zero = true;
    } else if (MODE_A == A_RELENC) {
        int b = grow >> 13;
        if (kbase < DIN)          p = src0 + ((size_t)((b << 10) + recv_s[row])) * DIN + kbase;
        else if (kbase < 2 * DIN) p = src0 + ((size_t)((b << 10) + send_s[row])) * DIN + (kbase - DIN);
        else                      special = true;
    } else if (MODE_A == A_RELPROP) {
        int b = grow >> 13;
        if (kbase < NF)           p = A + (size_t)grow * NF + kbase;
        else if (kbase < 2 * NF)  p = src0 + ((size_t)((b << 10) + recv_s[row])) * NF + (kbase - NF);
        else                      p = src0 + ((size_t)((b << 10) + send_s[row])) * NF + (kbase - 2 * NF);
    } else { // A_PARTPROP
        if (kbase < NF) p = A + (size_t)grow * NF + kbase;
        else            p = src0 + (size_t)grow * NF + (kbase - NF);
    }

    if (p) {
        const float4* q = reinterpret_cast<const float4*>(p);
#pragma unroll
        for (int j = 0; j < 4; ++j) {
            float4 u = q[j];
            x[4 * j] = u.x; x[4 * j + 1] = u.y; x[4 * j + 2] = u.z; x[4 * j + 3] = u.w;
        }
    } else {
#pragma unroll
        for (int j = 0; j < 16; ++j) x[j] = 0.f;
        if (MODE_A == A_RELENC && special && kbase == 2 * DIN) x[0] = A[grow]; // Ra, REL_D=1
        (void)zero;
    }

    uint32_t hi[8], lo[8];
#pragma unroll
    for (int j = 0; j < 8; ++j) {
        uint32_t h = packbf(x[2 * j], x[2 * j + 1]);
        hi[j] = h;
        float h0 = __uint_as_float(h << 16);
        float h1 = __uint_as_float(h & 0xFFFF0000u);
        lo[j] = packbf(x[2 * j] - h0, x[2 * j + 1] - h1);
    }
    {
        uint4* dh = reinterpret_cast<uint4*>(smem + AHI_OFF(s) + row * 80 + half * 32);
        dh[0] = make_uint4(hi[0], hi[1], hi[2], hi[3]);
        dh[1] = make_uint4(hi[4], hi[5], hi[6], hi[7]);
        uint4* dl = reinterpret_cast<uint4*>(smem + ALO_OFF(s) + row * 80 + half * 32);
        dl[0] = make_uint4(lo[0], lo[1], lo[2], lo[3]);
        dl[1] = make_uint4(lo[4], lo[5], lo[6], lo[7]);
    }

    // ---- W: 16 k2-rows x 128 n, each thread: 8 u32 ----
    {
        const int k2 = tid >> 4;
        const int nn = (tid & 15) * 8;
        const size_t gi = (size_t)(kt * 16 + k2) * 128 + nn;
        uint4 h0 = *reinterpret_cast<const uint4*>(Whp + gi);
        uint4 h1 = *reinterpret_cast<const uint4*>(Whp + gi + 4);
        uint4 l0 = *reinterpret_cast<const uint4*>(Wlp + gi);
        uint4 l1 = *reinterpret_cast<const uint4*>(Wlp + gi + 4);
        char* wb = smem + WHI_OFF(s) + k2 * 544 + nn * 4;
        reinterpret_cast<uint4*>(wb)[0] = h0;
        reinterpret_cast<uint4*>(wb)[1] = h1;
        char* lb = smem + WLO_OFF(s) + k2 * 544 + nn * 4;
        reinterpret_cast<uint4*>(lb)[0] = l0;
        reinterpret_cast<uint4*>(lb)[1] = l1;
    }
}

template<int MODE_A, int MODE_EPI>
__global__ __launch_bounds__(256, 2)
void mma_gemm(const float* __restrict__ A,
              const uint32_t* __restrict__ Whp, const uint32_t* __restrict__ Wlp,
              const float* __restrict__ bias, float* __restrict__ C,
              const float* __restrict__ src0,
              const int* __restrict__ recvp, const int* __restrict__ sendp,
              int K, int nchunk)
{
    extern __shared__ char smem[];
    const int tid  = threadIdx.x;
    const int wid  = tid >> 5;
    const int lane = tid & 31;
    const int row0 = blockIdx.x * 128;
    const int wm = wid & 1;    // 2 m-blocks of 64
    const int wn = wid >> 1;   // 4 n-blocks of 32

    float* bias_s = (float*)(smem + SM_BIAS);
    int* recv_s = (int*)(smem + SM_RECV);
    int* send_s = (int*)(smem + SM_SEND);
    if (tid < 128) {
        bias_s[tid] = bias[tid];
        if (MODE_A == A_RELENC || MODE_A == A_RELPROP) {
            recv_s[tid] = recvp[row0 + tid];
            send_s[tid] = sendp[row0 + tid];
        } else if (MODE_EPI == E_SCATTER) {
            recv_s[tid] = recvp[row0 + tid];
        }
    }
    __syncthreads();

    float acc[4][4][4];
#pragma unroll
    for (int f = 0; f < 4; ++f)
#pragma unroll
        for (int nf = 0; nf < 4; ++nf)
#pragma unroll
            for (int j = 0; j < 4; ++j) acc[f][nf][j] = 0.f;

    fill_tile<MODE_A>(smem, 0, 0, A, Whp, Wlp, src0, recv_s, send_s, row0, K, tid);
    __syncthreads();

    for (int kt = 0; kt < nchunk; ++kt) {
        const int s = kt & 1;
        if (kt + 1 < nchunk)
            fill_tile<MODE_A>(smem, s ^ 1, kt + 1, A, Whp, Wlp, src0, recv_s, send_s, row0, K, tid);

        const uint32_t* AH = (const uint32_t*)(smem + AHI_OFF(s));
        const uint32_t* AL = (const uint32_t*)(smem + ALO_OFF(s));
        const uint32_t* WH = (const uint32_t*)(smem + WHI_OFF(s));
        const uint32_t* WL = (const uint32_t*)(smem + WLO_OFF(s));

#pragma unroll
        for (int step = 0; step < 2; ++step) {
            uint32_t ah[4][4], al[4][4];
#pragma unroll
            for (int f = 0; f < 4; ++f) {
                int r = wm * 64 + f * 16 + (lane >> 2);
                int i0 = r * 20 + (lane & 3) + step * 8;
                ah[f][0] = AH[i0];       ah[f][1] = AH[i0 + 160];
                ah[f][2] = AH[i0 + 4];   ah[f][3] = AH[i0 + 164];
                al[f][0] = AL[i0];       al[f][1] = AL[i0 + 160];
                al[f][2] = AL[i0 + 4];   al[f][3] = AL[i0 + 164];
            }
#pragma unroll
            for (int nf = 0; nf < 4; ++nf) {
                int bi = (step * 8 + (lane & 3)) * 136 + wn * 32 + nf * 8 + (lane >> 2);
                uint32_t bh0 = WH[bi], bh1 = WH[bi + 544];
                uint32_t bl0 = WL[bi], bl1 = WL[bi + 544];
#pragma unroll
                for (int f = 0; f < 4; ++f) {
                    mma16816(acc[f][nf], ah[f], bh0, bh1);
                    mma16816(acc[f][nf], ah[f], bl0, bl1);
                    mma16816(acc[f][nf], al[f], bh0, bh1);
                }
            }
        }
        __syncthreads();
    }

    // ---- epilogue ----
    float bc0[4], bc1[4];
#pragma unroll
    for (int nf = 0; nf < 4; ++nf) {
        int c = wn * 32 + nf * 8 + (lane & 3) * 2;
        bc0[nf] = bias_s[c];
        bc1[nf] = bias_s[c + 1];
    }
#pragma unroll
    for (int f = 0; f < 4; ++f) {
        int rl0 = wm * 64 + f * 16 + (lane >> 2);
        int rl1 = rl0 + 8;
        int r0 = row0 + rl0;
        int r1 = row0 + rl1;
#pragma unroll
        for (int nf = 0; nf < 4; ++nf) {
            int c = wn * 32 + nf * 8 + (lane & 3) * 2;
            float v0 = acc[f][nf][0] + bc0[nf];
            float v1 = acc[f][nf][1] + bc1[nf];
            float v2 = acc[f][nf][2] + bc0[nf];
            float v3 = acc[f][nf][3] + bc1[nf];
            if (MODE_EPI == E_RELU) {
                *reinterpret_cast<float2*>(&C[(size_t)r0 * NF + c]) =
                    make_float2(fmaxf(v0, 0.f), fmaxf(v1, 0.f));
                *reinterpret_cast<float2*>(&C[(size_t)r1 * NF + c]) =
                    make_float2(fmaxf(v2, 0.f), fmaxf(v3, 0.f));
            } else if (MODE_EPI == E_RESID) {
                float2* p0 = reinterpret_cast<float2*>(&C[(size_t)r0 * NF + c]);
                float2* p1 = reinterpret_cast<float2*>(&C[(size_t)r1 * NF + c]);
                float2 o0 = *p0, o1 = *p1;
                *p0 = make_float2(fmaxf(v0 + o0.x, 0.f), fmaxf(v1 + o0.y, 0.f));
                *p1 = make_float2(fmaxf(v2 + o1.x, 0.f), fmaxf(v3 + o1.y, 0.f));
            } else { // E_SCATTER
                int b = r0 >> 13;
                float* d0 = &C[(size_t)((b << 10) + recv_s[rl0]) * NF + c];
                float* d1 = &C[(size_t)((b << 10) + recv_s[rl1]) * NF + c];
                atomicAdd(d0,     fmaxf(v0, 0.f));
                atomicAdd(d0 + 1, fmaxf(v1, 0.f));
                atomicAdd(d1,     fmaxf(v2, 0.f));
                atomicAdd(d1 + 1, fmaxf(v3, 0.f));
            }
        }
    }
}

// ---------------- final predictor layer: [8192,128] @ [128,3] + b -----------
__global__ void pred_final_kernel(const float* __restrict__ X, const float* __restrict__ W,
                                  const float* __restrict__ bias, float* __restrict__ out)
{
    __shared__ float Ws[NF * DOUT];
    __shared__ float bs[DOUT];
    int tid = threadIdx.x;
    for (int i = tid; i < NF * DOUT; i += blockDim.x) Ws[i] = W[i];
    if (tid < DOUT) bs[tid] = bias[tid];
    __syncthreads();
    int p = blockIdx.x * blockDim.x + tid;
    float a0 = bs[0], a1 = bs[1], a2 = bs[2];
    const float4* xp = reinterpret_cast<const float4*>(X + (size_t)p * NF);
#pragma unroll
    for (int k4 = 0; k4 < NF / 4; ++k4) {
        float4 x = xp[k4];
        int k = k4 * 4;
        a0 += x.x * Ws[k * 3 + 0] + x.y * Ws[(k + 1) * 3 + 0] +
              x.z * Ws[(k + 2) * 3 + 0] + x.w * Ws[(k + 3) * 3 + 0];
        a1 += x.x * Ws[k * 3 + 1] + x.y * Ws[(k + 1) * 3 + 1] +
              x.z * Ws[(k + 2) * 3 + 1] + x.w * Ws[(k + 3) * 3 + 1];
        a2 += x.x * Ws[k * 3 + 2] + x.y * Ws[(k + 1) * 3 + 2] +
              x.z * Ws[(k + 2) * 3 + 2] + x.w * Ws[(k + 3) * 3 + 2];
    }
    out[p * 3 + 0] = a0;
    out[p * 3 + 1] = a1;
    out[p * 3 + 2] = a2;
}

// ---------------- host orchestration ----------------------------------------
extern "C" void kernel_launch(void* const* d_in, const int* in_sizes, int n_in,
                              void* d_out, int out_size)
{
    const float* state = (const float*)d_in[0];
    const float* Rr    = (const float*)d_in[1];
    const float* Rs    = (const float*)d_in[2];
    const float* Ra    = (const float*)d_in[3];
    const float* pe_w0 = (const float*)d_in[5],  *pe_b0 = (const float*)d_in[6];
    const float* pe_w1 = (const float*)d_in[7],  *pe_b1 = (const float*)d_in[8];
    const float* re_w0 = (const float*)d_in[9],  *re_b0 = (const float*)d_in[10];
    const float* re_w1 = (const float*)d_in[11], *re_b1 = (const float*)d_in[12];
    const float* re_w2 = (const float*)d_in[13], *re_b2 = (const float*)d_in[14];
    const float* rp_w  = (const float*)d_in[15], *rp_b  = (const float*)d_in[16];
    const float* pp_w  = (const float*)d_in[17], *pp_b  = (const float*)d_in[18];
    const float* pr_w0 = (const float*)d_in[19], *pr_b0 = (const float*)d_in[20];
    const float* pr_w1 = (const float*)d_in[21], *pr_b1 = (const float*)d_in[22];
    float* out = (float*)d_out;

    float *buf0, *buf1, *relenc, *pencode, *peffect, *eagg, *ptmp;
    int *recv, *send;
    uint32_t *wh, *wl;
    cudaGetSymbolAddress((void**)&buf0,    g_buf0);
    cudaGetSymbolAddress((void**)&buf1,    g_buf1);
    cudaGetSymbolAddress((void**)&relenc,  g_relenc);
    cudaGetSymbolAddress((void**)&pencode, g_pencode);
    cudaGetSymbolAddress((void**)&peffect, g_peffect);
    cudaGetSymbolAddress((void**)&eagg,    g_eagg);
    cudaGetSymbolAddress((void**)&ptmp,    g_ptmp);
    cudaGetSymbolAddress((void**)&recv,    g_recv);
    cudaGetSymbolAddress((void**)&send,    g_send);
    cudaGetSymbolAddress((void**)&wh,      g_wh);
    cudaGetSymbolAddress((void**)&wl,      g_wl);

    cudaFuncSetAttribute(mma_gemm<A_PLAIN,    E_RELU>,    cudaFuncAttributeMaxDynamicSharedMemorySize, SMEM_TOTAL_B);
    cudaFuncSetAttribute(mma_gemm<A_RELENC,   E_RELU>,    cudaFuncAttributeMaxDynamicSharedMemorySize, SMEM_TOTAL_B);
    cudaFuncSetAttribute(mma_gemm<A_RELPROP,  E_SCATTER>, cudaFuncAttributeMaxDynamicSharedMemorySize, SMEM_TOTAL_B);
    cudaFuncSetAttribute(mma_gemm<A_PARTPROP, E_RESID>,   cudaFuncAttributeMaxDynamicSharedMemorySize, SMEM_TOTAL_B);

    // 1) one-hot -> indices
    extract_idx_kernel<<<2048, 256>>>((const float4*)Rr, (const float4*)Rs, recv, send);

    // 2) weight transpose + split + pack (tiny)
    split_w_kernel<<<(16  * 128 + 255) / 256, 256>>>(pe_w0, wh + WO_PE0, wl + WO_PE0, 32, 32);
    split_w_kernel<<<(64  * 128 + 255) / 256, 256>>>(pe_w1, wh + WO_PE1, wl + WO_PE1, 128, 128);
    split_w_kernel<<<(48  * 128 + 255) / 256, 256>>>(re_w0, wh + WO_RE0, wl + WO_RE0, 65, 96);
    split_w_kernel<<<(64  * 128 + 255) / 256, 256>>>(re_w1, wh + WO_RE1, wl + WO_RE1, 128, 128);
    split_w_kernel<<<(64  * 128 + 255) / 256, 256>>>(re_w2, wh + WO_RE2, wl + WO_RE2, 128, 128);
    split_w_kernel<<<(192 * 128 + 255) / 256, 256>>>(rp_w,  wh + WO_RP,  wl + WO_RP,  384, 384);
    split_w_kernel<<<(128 * 128 + 255) / 256, 256>>>(pp_w,  wh + WO_PP,  wl + WO_PP,  256, 256);
    split_w_kernel<<<(64  * 128 + 255) / 256, 256>>>(pr_w0, wh + WO_PR0, wl + WO_PR0, 128, 128);

    // 3) relation encoder
    mma_gemm<A_RELENC, E_RELU><<<MREL / 128, 256, SMEM_TOTAL_B>>>(Ra, wh + WO_RE0, wl + WO_RE0, re_b0, buf0, state, recv, send, 65, 3);
    mma_gemm<A_PLAIN,  E_RELU><<<MREL / 128, 256, SMEM_TOTAL_B>>>(buf0, wh + WO_RE1, wl + WO_RE1, re_b1, buf1, nullptr, nullptr, nullptr, 128, 4);
    mma_gemm<A_PLAIN,  E_RELU><<<MREL / 128, 256, SMEM_TOTAL_B>>>(buf1, wh + WO_RE2, wl + WO_RE2, re_b2, relenc, nullptr, nullptr, nullptr, 128, 4);

    // 4) particle encoder
    mma_gemm<A_PLAIN, E_RELU><<<MPART / 128, 256, SMEM_TOTAL_B>>>(state, wh + WO_PE0, wl + WO_PE0, pe_b0, ptmp, nullptr, nullptr, nullptr, 32, 1);
    mma_gemm<A_PLAIN, E_RELU><<<MPART / 128, 256, SMEM_TOTAL_B>>>(ptmp, wh + WO_PE1, wl + WO_PE1, pe_b1, pencode, nullptr, nullptr, nullptr, 128, 4);

    // 5) propagation
    zero_kernel<<<MPART * NF / 4 / 256, 256>>>((float4*)peffect);
    for (int s = 0; s < PSTEPS; ++s) {
        zero_kernel<<<MPART * NF / 4 / 256, 256>>>((float4*)eagg);
        mma_gemm<A_RELPROP, E_SCATTER><<<MREL / 128, 256, SMEM_TOTAL_B>>>(relenc, wh + WO_RP, wl + WO_RP, rp_b, eagg, peffect, recv, send, 384, 12);
        mma_gemm<A_PARTPROP, E_RESID><<<MPART / 128, 256, SMEM_TOTAL_B>>>(pencode, wh + WO_PP, wl + WO_PP, pp_b, peffect, eagg, nullptr, nullptr, 256, 8);
    }

    // 6) predictor
    mma_gemm<A_PLAIN, E_RELU><<<MPART / 128, 256, SMEM_TOTAL_B>>>(peffect, wh + WO_PR0, wl + WO_PR0, pr_b0, ptmp, nullptr, nullptr, nullptr, 128, 4);
    pred_final_kernel<<<MPART / 256, 256>>>(ptmp, pr_w1, pr_b1, out);
}

// round 4
// speedup vs baseline: 2.4248x; 1.0677x over previous
#include <cuda_runtime.h>
#include <cuda_bf16.h>
#include <cstdint>

#define BB    8
#define NN    1024
#define RR    8192
#define DIN   32
#define NF    128
#define DOUT  3
#define PSTEPS 3
#define MREL  (BB * RR)   // 65536
#define MPART (BB * NN)   // 8192

// ---------------- scratch (device globals) ----------------------------------
// rel-sized bf16-plane buffers (u32 = bf16x2; row = 64 hi + 64 lo u32)
__device__ uint32_t g_p0[MREL * NF];      // 32 MB
__device__ uint32_t g_p1[MREL * NF];      // 32 MB
__device__ float    g_relbase[MREL * NF]; // 32 MB fp32 (relenc @ rp_top + rp_b)
__device__ uint32_t g_ptmpP[MPART * NF];  // pe-chain planes / later fp32 reuse
__device__ uint32_t g_pencP[MPART * NF];  // pencode planes
__device__ uint32_t g_peffP[MPART * NF];  // peffect planes
__device__ float    g_peffect[MPART * NF];
__device__ float    g_pbase[MPART * NF];
__device__ float    g_eagg[MPART * NF];
__device__ int      g_recv[MREL];
__device__ int      g_send[MREL];
// packed weights: [Kpad/2][128] u32 (bf16x2 of k,k+1 per col n), hi & lo planes
#define WT_U32 81920
__device__ uint32_t g_wh[WT_U32];
__device__ uint32_t g_wl[WT_U32];
#define WO_PE0 0        // Kpad 32
#define WO_PE1 2048     // 128
#define WO_RE0 10240    // 96 (K=65)
#define WO_RE1 16384    // 128
#define WO_RE2 24576    // 128
#define WO_RP  32768    // 384
#define WO_PP  57344    // 256
#define WO_PR0 73728    // 128
#define CHUNK_U32 2048  // one K=32 chunk of W = 16 k2-rows * 128

// ---------------- helpers ----------------------------------------------------
__device__ __forceinline__ uint32_t packbf(float vlo, float vhi) {
    uint32_t r;
    asm("cvt.rn.bf16x2.f32 %0, %1, %2;" : "=r"(r) : "f"(vhi), "f"(vlo));
    return r;
}
__device__ __forceinline__ void mma16816(float* d, const uint32_t* a, uint32_t b0, uint32_t b1) {
    asm volatile("mma.sync.aligned.m16n8k16.row.col.f32.bf16.bf16.f32 "
                 "{%0,%1,%2,%3}, {%4,%5,%6,%7}, {%8,%9}, {%0,%1,%2,%3};"
                 : "+f"(d[0]), "+f"(d[1]), "+f"(d[2]), "+f"(d[3])
                 : "r"(a[0]), "r"(a[1]), "r"(a[2]), "r"(a[3]), "r"(b0), "r"(b1));
}

// ---------------- index extraction from dense one-hot Rr/Rs -----------------
__global__ void extract_idx_kernel(const float4* __restrict__ Rr,
                                   const float4* __restrict__ Rs,
                                   int* __restrict__ recv, int* __restrict__ send)
{
    const long long total = (long long)BB * NN * RR / 4;
    const long long stride = (long long)gridDim.x * blockDim.x;
    for (long long i = blockIdx.x * (long long)blockDim.x + threadIdx.x;
         i < total; i += stride) {
        float4 v = Rr[i];
        if (v.x != 0.f || v.y != 0.f || v.z != 0.f || v.w != 0.f) {
            long long e = i * 4;
            int b = (int)(e >> 23);
            int n = (int)((e >> 13) & (NN - 1));
            int r = (int)(e & (RR - 1));
            int* o = recv + b * RR + r;
            if (v.x != 0.f) o[0] = n;
            if (v.y != 0.f) o[1] = n;
            if (v.z != 0.f) o[2] = n;
            if (v.w != 0.f) o[3] = n;
        }
        float4 w = Rs[i];
        if (w.x != 0.f || w.y != 0.f || w.z != 0.f || w.w != 0.f) {
            long long e = i * 4;
            int b = (int)(e >> 23);
            int n = (int)((e >> 13) & (NN - 1));
            int r = (int)(e & (RR - 1));
            int* o = send + b * RR + r;
            if (w.x != 0.f) o[0] = n;
            if (w.y != 0.f) o[1] = n;
            if (w.z != 0.f) o[2] = n;
            if (w.w != 0.f) o[3] = n;
        }
    }
}

// zero peffect (fp32) + eagg in one pass
__global__ void zero_two_kernel(float4* __restrict__ a, float4* __restrict__ b) {
    int i = blockIdx.x * blockDim.x + threadIdx.x;
    a[i] = make_float4(0.f, 0.f, 0.f, 0.f);
    b[i] = make_float4(0.f, 0.f, 0.f, 0.f);
}

// ---------------- all weights: transpose + split + pack, one kernel ---------
__global__ void split_all_kernel(const float* __restrict__ p0, const float* __restrict__ p1,
                                 const float* __restrict__ p2, const float* __restrict__ p3,
                                 const float* __restrict__ p4, const float* __restrict__ p5,
                                 const float* __restrict__ p6, const float* __restrict__ p7,
                                 uint32_t* __restrict__ hi, uint32_t* __restrict__ lo)
{
    int idx = blockIdx.x * blockDim.x + threadIdx.x;
    if (idx >= WT_U32) return;
    const float* w; int K, local;
    if      (idx < 2048)  { w = p0; K = 32;  local = idx; }
    else if (idx < 10240) { w = p1; K = 128; local = idx - 2048; }
    else if (idx < 16384) { w = p2; K = 65;  local = idx - 10240; }
    else if (idx < 24576) { w = p3; K = 128; local = idx - 16384; }
    else if (idx < 32768) { w = p4; K = 128; local = idx - 24576; }
    else if (idx < 57344) { w = p5; K = 384; local = idx - 32768; }
    else if (idx < 73728) { w = p6; K = 256; local = idx - 57344; }
    else                  { w = p7; K = 128; local = idx - 73728; }
    int k2 = local >> 7, n = local & 127;
    int k0 = 2 * k2;
    float v0 = (k0 < K)     ? w[(size_t)k0 * 128 + n]       : 0.f;
    float v1 = (k0 + 1 < K) ? w[(size_t)(k0 + 1) * 128 + n] : 0.f;
    uint32_t h = packbf(v0, v1);
    float h0 = __uint_as_float(h << 16);
    float h1 = __uint_as_float(h & 0xFFFF0000u);
    hi[idx] = h;
    lo[idx] = packbf(v0 - h0, v1 - h1);
}

// ---------------- step-1 relation scatter: eagg += relu(rel_base) -----------
__global__ void scatter_base_kernel(const float* __restrict__ base,
                                    const int* __restrict__ recv,
                                    float* __restrict__ eagg)
{
    const int tid = threadIdx.x;
    const int row = blockIdx.x * 128 + (tid >> 1);
    const int cof = (tid & 1) * 64;
    const int b = row >> 13;
    float* dst = eagg + ((size_t)((b << 10) + recv[row])) * NF + cof;
    const float4* src = reinterpret_cast<const float4*>(base + (size_t)row * NF + cof);
#pragma unroll
    for (int j = 0; j < 16; ++j) {
        float4 v = src[j];
        atomicAdd(dst + 4 * j,     fmaxf(v.x, 0.f));
        atomicAdd(dst + 4 * j + 1, fmaxf(v.y, 0.f));
        atomicAdd(dst + 4 * j + 2, fmaxf(v.z, 0.f));
        atomicAdd(dst + 4 * j + 3, fmaxf(v.w, 0.f));
    }
}

// ---------------- fused mma.sync GEMM ----------------------------------------
enum { A_F32 = 0, A_BF = 1, A_RELENC = 2, A_EFFGATHER = 3 };
enum { E_RELU_F32 = 0, E_RELU_BF = 1, E_BASE = 2, E_SCATTER_BASE = 3, E_RESID = 4 };

#define SM_BIAS 0
#define SM_RECV 512
#define SM_SEND 1024
#define SM_A    1536
#define AHI_OFF(s) (SM_A + (s) * 10240)
#define ALO_OFF(s) (SM_A + 20480 + (s) * 10240)
#define SM_W    (SM_A + 40960)
#define WHI_OFF(s) (SM_W + (s) * 8704)
#define WLO_OFF(s) (SM_W + 17408 + (s) * 8704)
#define SMEM_TOTAL_B (SM_W + 34816)   // 77312 bytes

template<int MODE_A>
__device__ __forceinline__ void fill_tile(
    char* smem, int s, int kt,
    const void* __restrict__ Av,
    const uint32_t* __restrict__ Whp, const uint32_t* __restrict__ Wlp,
    const float* __restrict__ srcf, const uint32_t* __restrict__ srcp,
    const int* recv_s, const int* send_s,
    int row0, int K, int tid)
{
    const int row   = tid >> 1;
    const int half  = tid & 1;
    const int kbase = kt * 32 + half * 16;
    const int grow  = row0 + row;

    uint4 hA0, hA1, lA0, lA1;

    if (MODE_A == A_BF || MODE_A == A_EFFGATHER) {
        const uint32_t* Xp;
        int k2;
        if (MODE_A == A_BF) {
            Xp = (const uint32_t*)Av + (size_t)grow * 128;
            k2 = kbase >> 1;
        } else {
            int b = grow >> 13;
            int idx;
            if (kbase < NF) { idx = (b << 10) + recv_s[row]; k2 = kbase >> 1; }
            else            { idx = (b << 10) + send_s[row]; k2 = (kbase - NF) >> 1; }
            Xp = srcp + (size_t)idx * 128;
        }
        hA0 = *reinterpret_cast<const uint4*>(Xp + k2);
        hA1 = *reinterpret_cast<const uint4*>(Xp + k2 + 4);
        lA0 = *reinterpret_cast<const uint4*>(Xp + 64 + k2);
        lA1 = *reinterpret_cast<const uint4*>(Xp + 64 + k2 + 4);
    } else {
        float x[16];
        const float* p = nullptr;
        bool special = false;
        if (MODE_A == A_F32) {
            if (kbase < K) p = (const float*)Av + (size_t)grow * K + kbase;
        } else { // A_RELENC
            int b = grow >> 13;
            if (kbase < DIN)          p = srcf + ((size_t)((b << 10) + recv_s[row])) * DIN + kbase;
            else if (kbase < 2 * DIN) p = srcf + ((size_t)((b << 10) + send_s[row])) * DIN + (kbase - DIN);
            else                      special = true;
        }
        if (p) {
            const float4* q = reinterpret_cast<const float4*>(p);
#pragma unroll
            for (int j = 0; j < 4; ++j) {
                float4 u = q[j];
                x[4 * j] = u.x; x[4 * j + 1] = u.y; x[4 * j + 2] = u.z; x[4 * j + 3] = u.w;
            }
        } else {
#pragma unroll
            for (int j = 0; j < 16; ++j) x[j] = 0.f;
            if (MODE_A == A_RELENC && special && kbase == 2 * DIN)
                x[0] = ((const float*)Av)[grow]; // Ra, REL_D=1
        }
        uint32_t hi[8], lo[8];
#pragma unroll
        for (int j = 0; j < 8; ++j) {
            uint32_t h = packbf(x[2 * j], x[2 * j + 1]);
            hi[j] = h;
            float h0 = __uint_as_float(h << 16);
            float h1 = __uint_as_float(h & 0xFFFF0000u);
            lo[j] = packbf(x[2 * j] - h0, x[2 * j + 1] - h1);
        }
        hA0 = make_uint4(hi[0], hi[1], hi[2], hi[3]);
        hA1 = make_uint4(hi[4], hi[5], hi[6], hi[7]);
        lA0 = make_uint4(lo[0], lo[1], lo[2], lo[3]);
        lA1 = make_uint4(lo[4], lo[5], lo[6], lo[7]);
    }
    {
        uint4* dh = reinterpret_cast<uint4*>(smem + AHI_OFF(s) + row * 80 + half * 32);
        dh[0] = hA0; dh[1] = hA1;
        uint4* dl = reinterpret_cast<uint4*>(smem + ALO_OFF(s) + row * 80 + half * 32);
        dl[0] = lA0; dl[1] = lA1;
    }
    // ---- W: 16 k2-rows x 128 n ----
    {
        const int k2 = tid >> 4;
        const int nn = (tid & 15) * 8;
        const size_t gi = (size_t)(kt * 16 + k2) * 128 + nn;
        uint4 h0 = *reinterpret_cast<const uint4*>(Whp + gi);
        uint4 h1 = *reinterpret_cast<const uint4*>(Whp + gi + 4);
        uint4 l0 = *reinterpret_cast<const uint4*>(Wlp + gi);
        uint4 l1 = *reinterpret_cast<const uint4*>(Wlp + gi + 4);
        char* wb = smem + WHI_OFF(s) + k2 * 544 + nn * 4;
        reinterpret_cast<uint4*>(wb)[0] = h0;
        reinterpret_cast<uint4*>(wb)[1] = h1;
        char* lb = smem + WLO_OFF(s) + k2 * 544 + nn * 4;
        reinterpret_cast<uint4*>(lb)[0] = l0;
        reinterpret_cast<uint4*>(lb)[1] = l1;
    }
}

template<int MODE_A, int MODE_EPI>
__global__ __launch_bounds__(256, 2)
void mma_gemm(const void* __restrict__ Av,
              const uint32_t* __restrict__ Whp, const uint32_t* __restrict__ Wlp,
              const float* __restrict__ bias, void* __restrict__ C,
              const float* __restrict__ base,
              const float* __restrict__ srcf, const uint32_t* __restrict__ srcp,
              uint32_t* __restrict__ C2, float* __restrict__ eaggz,
              const int* __restrict__ recvp, const int* __restrict__ sendp,
              int K, int nchunk)
{
    extern __shared__ char smem[];
    const int tid  = threadIdx.x;
    const int wid  = tid >> 5;
    const int lane = tid & 31;
    const int row0 = blockIdx.x * 128;
    const int wm = wid & 1;
    const int wn = wid >> 1;

    float* bias_s = (float*)(smem + SM_BIAS);
    int* recv_s = (int*)(smem + SM_RECV);
    int* send_s = (int*)(smem + SM_SEND);
    if (tid < 128) {
        if (MODE_EPI == E_RELU_F32 || MODE_EPI == E_RELU_BF || MODE_EPI == E_BASE)
            bias_s[tid] = bias[tid];
        if (MODE_A == A_RELENC || MODE_A == A_EFFGATHER) {
            recv_s[tid] = recvp[row0 + tid];
            send_s[tid] = sendp[row0 + tid];
        }
    }
    __syncthreads();

    float acc[4][4][4];
#pragma unroll
    for (int f = 0; f < 4; ++f)
#pragma unroll
        for (int nf = 0; nf < 4; ++nf)
#pragma unroll
            for (int j = 0; j < 4; ++j) acc[f][nf][j] = 0.f;

    fill_tile<MODE_A>(smem, 0, 0, Av, Whp, Wlp, srcf, srcp, recv_s, send_s, row0, K, tid);
    __syncthreads();

    for (int kt = 0; kt < nchunk; ++kt) {
        const int s = kt & 1;
        if (kt + 1 < nchunk)
            fill_tile<MODE_A>(smem, s ^ 1, kt + 1, Av, Whp, Wlp, srcf, srcp, recv_s, send_s, row0, K, tid);

        const uint32_t* AH = (const uint32_t*)(smem + AHI_OFF(s));
        const uint32_t* AL = (const uint32_t*)(smem + ALO_OFF(s));
        const uint32_t* WH = (const uint32_t*)(smem + WHI_OFF(s));
        const uint32_t* WL = (const uint32_t*)(smem + WLO_OFF(s));

#pragma unroll
        for (int step = 0; step < 2; ++step) {
            uint32_t ah[4][4], al[4][4];
#pragma unroll
            for (int f = 0; f < 4; ++f) {
                int r = wm * 64 + f * 16 + (lane >> 2);
                int i0 = r * 20 + (lane & 3) + step * 8;
                ah[f][0] = AH[i0];       ah[f][1] = AH[i0 + 160];
                ah[f][2] = AH[i0 + 4];   ah[f][3] = AH[i0 + 164];
                al[f][0] = AL[i0];       al[f][1] = AL[i0 + 160];
                al[f][2] = AL[i0 + 4];   al[f][3] = AL[i0 + 164];
            }
#pragma unroll
            for (int nf = 0; nf < 4; ++nf) {
                int bi = (step * 8 + (lane & 3)) * 136 + wn * 32 + nf * 8 + (lane >> 2);
                uint32_t bh0 = WH[bi], bh1 = WH[bi + 544];
                uint32_t bl0 = WL[bi], bl1 = WL[bi + 544];
#pragma unroll
                for (int f = 0; f < 4; ++f) {
                    mma16816(acc[f][nf], ah[f], bh0, bh1);
                    mma16816(acc[f][nf], ah[f], bl0, bl1);
                    mma16816(acc[f][nf], al[f], bh0, bh1);
                }
            }
        }
        __syncthreads();
    }

    // ---- epilogue ----
    float bc0[4], bc1[4];
    if (MODE_EPI == E_RELU_F32 || MODE_EPI == E_RELU_BF || MODE_EPI == E_BASE) {
#pragma unroll
        for (int nf = 0; nf < 4; ++nf) {
            int c = wn * 32 + nf * 8 + (lane & 3) * 2;
            bc0[nf] = bias_s[c];
            bc1[nf] = bias_s[c + 1];
        }
    }
#pragma unroll
    for (int f = 0; f < 4; ++f) {
        int rl0 = wm * 64 + f * 16 + (lane >> 2);
        int rl1 = rl0 + 8;
        int r0 = row0 + rl0;
        int r1 = row0 + rl1;
#pragma unroll
        for (int nf = 0; nf < 4; ++nf) {
            int c = wn * 32 + nf * 8 + (lane & 3) * 2;
            float v0 = acc[f][nf][0];
            float v1 = acc[f][nf][1];
            float v2 = acc[f][nf][2];
            float v3 = acc[f][nf][3];
            if (MODE_EPI == E_RELU_F32 || MODE_EPI == E_RELU_BF || MODE_EPI == E_BASE) {
                v0 += bc0[nf]; v1 += bc1[nf]; v2 += bc0[nf]; v3 += bc1[nf];
            }
            if (MODE_EPI == E_RELU_F32) {
                float* CF = (float*)C;
                *reinterpret_cast<float2*>(&CF[(size_t)r0 * NF + c]) =
                    make_float2(fmaxf(v0, 0.f), fmaxf(v1, 0.f));
                *reinterpret_cast<float2*>(&CF[(size_t)r1 * NF + c]) =
                    make_float2(fmaxf(v2, 0.f), fmaxf(v3, 0.f));
            } else if (MODE_EPI == E_RELU_BF) {
                uint32_t* P = (uint32_t*)C;
                float a0 = fmaxf(v0, 0.f), a1 = fmaxf(v1, 0.f);
                float a2 = fmaxf(v2, 0.f), a3 = fmaxf(v3, 0.f);
                uint32_t h0 = packbf(a0, a1);
                uint32_t h1 = packbf(a2, a3);
                P[(size_t)r0 * 128 + (c >> 1)] = h0;
                P[(size_t)r1 * 128 + (c >> 1)] = h1;
                P[(size_t)r0 * 128 + 64 + (c >> 1)] =
                    packbf(a0 - __uint_as_float(h0 << 16), a1 - __uint_as_float(h0 & 0xFFFF0000u));
                P[(size_t)r1 * 128 + 64 + (c >> 1)] =
                    packbf(a2 - __uint_as_float(h1 << 16), a3 - __uint_as_float(h1 & 0xFFFF0000u));
            } else if (MODE_EPI == E_BASE) {
                float* CF = (float*)C;
                *reinterpret_cast<float2*>(&CF[(size_t)r0 * NF + c]) = make_float2(v0, v1);
                *reinterpret_cast<float2*>(&CF[(size_t)r1 * NF + c]) = make_float2(v2, v3);
            } else if (MODE_EPI == E_SCATTER_BASE) {
                float2 s0 = *reinterpret_cast<const float2*>(&base[(size_t)r0 * NF + c]);
                float2 s1 = *reinterpret_cast<const float2*>(&base[(size_t)r1 * NF + c]);
                int b = r0 >> 13;
                float* CF = (float*)C;
                float* d0 = &CF[(size_t)((b << 10) + recv_s[rl0]) * NF + c];
                float* d1 = &CF[(size_t)((b << 10) + recv_s[rl1]) * NF + c];
                atomicAdd(d0,     fmaxf(v0 + s0.x, 0.f));
                atomicAdd(d0 + 1, fmaxf(v1 + s0.y, 0.f));
                atomicAdd(d1,     fmaxf(v2 + s1.x, 0.f));
                atomicAdd(d1 + 1, fmaxf(v3 + s1.y, 0.f));
            } else { // E_RESID: v + pbase + prev -> relu -> fp32 + planes
                float* CF = (float*)C;
                float2 b0 = *reinterpret_cast<const float2*>(&base[(size_t)r0 * NF + c]);
                float2 b1 = *reinterpret_cast<const float2*>(&base[(size_t)r1 * NF + c]);
                float2 p0 = *reinterpret_cast<const float2*>(&CF[(size_t)r0 * NF + c]);
                float2 p1 = *reinterpret_cast<const float2*>(&CF[(size_t)r1 * NF + c]);
                float a0 = fmaxf(v0 + b0.x + p0.x, 0.f);
                float a1 = fmaxf(v1 + b0.y + p0.y, 0.f);
                float a2 = fmaxf(v2 + b1.x + p1.x, 0.f);
                float a3 = fmaxf(v3 + b1.y + p1.y, 0.f);
                *reinterpret_cast<float2*>(&CF[(size_t)r0 * NF + c]) = make_float2(a0, a1);
                *reinterpret_cast<float2*>(&CF[(size_t)r1 * NF + c]) = make_float2(a2, a3);
                uint32_t h0 = packbf(a0, a1);
                uint32_t h1 = packbf(a2, a3);
                C2[(size_t)r0 * 128 + (c >> 1)] = h0;
                C2[(size_t)r1 * 128 + (c >> 1)] = h1;
                C2[(size_t)r0 * 128 + 64 + (c >> 1)] =
                    packbf(a0 - __uint_as_float(h0 << 16), a1 - __uint_as_float(h0 & 0xFFFF0000u));
                C2[(size_t)r1 * 128 + 64 + (c >> 1)] =
                    packbf(a2 - __uint_as_float(h1 << 16), a3 - __uint_as_float(h1 & 0xFFFF0000u));
            }
        }
    }
    // zero eagg rows for the next step (all fill reads finished before last sync)
    if (MODE_EPI == E_RESID) {
        float4* z = reinterpret_cast<float4*>(eaggz + (size_t)(row0 + (tid >> 1)) * NF + (tid & 1) * 64);
#pragma unroll
        for (int j = 0; j < 16; ++j) z[j] = make_float4(0.f, 0.f, 0.f, 0.f);
    }
}

// ---------------- final predictor layer: [8192,128] @ [128,3] + b -----------
__global__ void pred_final_kernel(const float* __restrict__ X, const float* __restrict__ W,
                                  const float* __restrict__ bias, float* __restrict__ out)
{
    __shared__ float Ws[NF * DOUT];
    __shared__ float bs[DOUT];
    int tid = threadIdx.x;
    for (int i = tid; i < NF * DOUT; i += blockDim.x) Ws[i] = W[i];
    if (tid < DOUT) bs[tid] = bias[tid];
    __syncthreads();
    int p = blockIdx.x * blockDim.x + tid;
    float a0 = bs[0], a1 = bs[1], a2 = bs[2];
    const float4* xp = reinterpret_cast<const float4*>(X + (size_t)p * NF);
#pragma unroll
    for (int k4 = 0; k4 < NF / 4; ++k4) {
        float4 x = xp[k4];
        int k = k4 * 4;
        a0 += x.x * Ws[k * 3 + 0] + x.y * Ws[(k + 1) * 3 + 0] +
              x.z * Ws[(k + 2) * 3 + 0] + x.w * Ws[(k + 3) * 3 + 0];
        a1 += x.x * Ws[k * 3 + 1] + x.y * Ws[(k + 1) * 3 + 1] +
              x.z * Ws[(k + 2) * 3 + 1] + x.w * Ws[(k + 3) * 3 + 1];
        a2 += x.x * Ws[k * 3 + 2] + x.y * Ws[(k + 1) * 3 + 2] +
              x.z * Ws[(k + 2) * 3 + 2] + x.w * Ws[(k + 3) * 3 + 2];
    }
    out[p * 3 + 0] = a0;
    out[p * 3 + 1] = a1;
    out[p * 3 + 2] = a2;
}

// ---------------- host orchestration ----------------------------------------
extern "C" void kernel_launch(void* const* d_in, const int* in_sizes, int n_in,
                              void* d_out, int out_size)
{
    const float* state = (const float*)d_in[0];
    const float* Rr    = (const float*)d_in[1];
    const float* Rs    = (const float*)d_in[2];
    const float* Ra    = (const float*)d_in[3];
    const float* pe_w0 = (const float*)d_in[5],  *pe_b0 = (const float*)d_in[6];
    const float* pe_w1 = (const float*)d_in[7],  *pe_b1 = (const float*)d_in[8];
    const float* re_w0 = (const float*)d_in[9],  *re_b0 = (const float*)d_in[10];
    const float* re_w1 = (const float*)d_in[11], *re_b1 = (const float*)d_in[12];
    const float* re_w2 = (const float*)d_in[13], *re_b2 = (const float*)d_in[14];
    const float* rp_w  = (const float*)d_in[15], *rp_b  = (const float*)d_in[16];
    const float* pp_w  = (const float*)d_in[17], *pp_b  = (const float*)d_in[18];
    const float* pr_w0 = (const float*)d_in[19], *pr_b0 = (const float*)d_in[20];
    const float* pr_w1 = (const float*)d_in[21], *pr_b1 = (const float*)d_in[22];
    float* out = (float*)d_out;

    uint32_t *p0, *p1, *ptmpP, *pencP, *peffP, *wh, *wl;
    float *relbase, *peffect, *pbase, *eagg;
    int *recv, *send;
    cudaGetSymbolAddress((void**)&p0,      g_p0);
    cudaGetSymbolAddress((void**)&p1,      g_p1);
    cudaGetSymbolAddress((void**)&relbase, g_relbase);
    cudaGetSymbolAddress((void**)&ptmpP,   g_ptmpP);
    cudaGetSymbolAddress((void**)&pencP,   g_pencP);
    cudaGetSymbolAddress((void**)&peffP,   g_peffP);
    cudaGetSymbolAddress((void**)&peffect, g_peffect);
    cudaGetSymbolAddress((void**)&pbase,   g_pbase);
    cudaGetSymbolAddress((void**)&eagg,    g_eagg);
    cudaGetSymbolAddress((void**)&recv,    g_recv);
    cudaGetSymbolAddress((void**)&send,    g_send);
    cudaGetSymbolAddress((void**)&wh,      g_wh);
    cudaGetSymbolAddress((void**)&wl,      g_wl);

    cudaFuncSetAttribute(mma_gemm<A_RELENC,    E_RELU_BF>,     cudaFuncAttributeMaxDynamicSharedMemorySize, SMEM_TOTAL_B);
    cudaFuncSetAttribute(mma_gemm<A_BF,        E_RELU_BF>,     cudaFuncAttributeMaxDynamicSharedMemorySize, SMEM_TOTAL_B);
    cudaFuncSetAttribute(mma_gemm<A_F32,       E_RELU_BF>,     cudaFuncAttributeMaxDynamicSharedMemorySize, SMEM_TOTAL_B);
    cudaFuncSetAttribute(mma_gemm<A_BF,        E_BASE>,        cudaFuncAttributeMaxDynamicSharedMemorySize, SMEM_TOTAL_B);
    cudaFuncSetAttribute(mma_gemm<A_F32,       E_RESID>,       cudaFuncAttributeMaxDynamicSharedMemorySize, SMEM_TOTAL_B);
    cudaFuncSetAttribute(mma_gemm<A_EFFGATHER, E_SCATTER_BASE>,cudaFuncAttributeMaxDynamicSharedMemorySize, SMEM_TOTAL_B);
    cudaFuncSetAttribute(mma_gemm<A_BF,        E_RELU_F32>,    cudaFuncAttributeMaxDynamicSharedMemorySize, SMEM_TOTAL_B);

    // 1) one-hot -> indices
    extract_idx_kernel<<<2048, 256>>>((const float4*)Rr, (const float4*)Rs, recv, send);

    // 2) all weights: transpose + split + pack (one launch)
    split_all_kernel<<<WT_U32 / 256, 256>>>(pe_w0, pe_w1, re_w0, re_w1, re_w2, rp_w, pp_w, pr_w0, wh, wl);

    // 3) relation encoder (outputs bf16 planes)
    mma_gemm<A_RELENC, E_RELU_BF><<<MREL / 128, 256, SMEM_TOTAL_B>>>(
        Ra, wh + WO_RE0, wl + WO_RE0, re_b0, p0, nullptr, state, nullptr, nullptr, nullptr, recv, send, 65, 3);
    mma_gemm<A_BF, E_RELU_BF><<<MREL / 128, 256, SMEM_TOTAL_B>>>(
        p0, wh + WO_RE1, wl + WO_RE1, re_b1, p1, nullptr, nullptr, nullptr, nullptr, nullptr, nullptr, nullptr, 128, 4);
    mma_gemm<A_BF, E_RELU_BF><<<MREL / 128, 256, SMEM_TOTAL_B>>>(
        p1, wh + WO_RE2, wl + WO_RE2, re_b2, p0, nullptr, nullptr, nullptr, nullptr, nullptr, nullptr, nullptr, 128, 4);

    // 4) particle encoder (outputs bf16 planes)
    mma_gemm<A_F32, E_RELU_BF><<<MPART / 128, 256, SMEM_TOTAL_B>>>(
        state, wh + WO_PE0, wl + WO_PE0, pe_b0, ptmpP, nullptr, nullptr, nullptr, nullptr, nullptr, nullptr, nullptr, 32, 1);
    mma_gemm<A_BF, E_RELU_BF><<<MPART / 128, 256, SMEM_TOTAL_B>>>(
        ptmpP, wh + WO_PE1, wl + WO_PE1, pe_b1, pencP, nullptr, nullptr, nullptr, nullptr, nullptr, nullptr, nullptr, 128, 4);

    // 5) loop-invariant bases
    mma_gemm<A_BF, E_BASE><<<MREL / 128, 256, SMEM_TOTAL_B>>>(
        p0, wh + WO_RP, wl + WO_RP, rp_b, relbase, nullptr, nullptr, nullptr, nullptr, nullptr, nullptr, nullptr, 128, 4);
    mma_gemm<A_BF, E_BASE><<<MPART / 128, 256, SMEM_TOTAL_B>>>(
        pencP, wh + WO_PP, wl + WO_PP, pp_b, pbase, nullptr, nullptr, nullptr, nullptr, nullptr, nullptr, nullptr, 128, 4);

    // 6) propagation
    zero_two_kernel<<<MPART * NF / 4 / 256, 256>>>((float4*)peffect, (float4*)eagg);
    // step 1: effects are zero -> relation GEMM collapses to scatter(relu(base))
    scatter_base_kernel<<<MREL / 128, 256>>>(relbase, recv, eagg);
    mma_gemm<A_F32, E_RESID><<<MPART / 128, 256, SMEM_TOTAL_B>>>(
        eagg, wh + WO_PP + 4 * CHUNK_U32, wl + WO_PP + 4 * CHUNK_U32, nullptr, peffect, pbase,
        nullptr, nullptr, peffP, eagg, nullptr, nullptr, 128, 4);
    // steps 2..3
    for (int s = 1; s < PSTEPS; ++s) {
        mma_gemm<A_EFFGATHER, E_SCATTER_BASE><<<MREL / 128, 256, SMEM_TOTAL_B>>>(
            nullptr, wh + WO_RP + 4 * CHUNK_U32, wl + WO_RP + 4 * CHUNK_U32, nullptr, eagg, relbase,
            nullptr, peffP, nullptr, nullptr, recv, send, 256, 8);
        mma_gemm<A_F32, E_RESID><<<MPART / 128, 256, SMEM_TOTAL_B>>>(
            eagg, wh + WO_PP + 4 * CHUNK_U32, wl + WO_PP + 4 * CHUNK_U32, nullptr, peffect, pbase,
            nullptr, nullptr, peffP, eagg, nullptr, nullptr, 128, 4);
    }

    // 7) predictor (A = peffect planes; ptmpP reused as fp32 scratch)
    mma_gemm<A_BF, E_RELU_F32><<<MPART / 128, 256, SMEM_TOTAL_B>>>(
        peffP, wh + WO_PR0, wl + WO_PR0, pr_b0, ptmpP, nullptr, nullptr, nullptr, nullptr, nullptr, nullptr, nullptr, 128, 4);
    pred_final_kernel<<<MPART / 256, 256>>>((const float*)ptmpP, pr_w1, pr_b1, out);
}